// round 3
// baseline (speedup 1.0000x reference)
#include <cuda_runtime.h>
#include <cuda_bf16.h>
#include <cstdint>
#include <cstddef>
#include <math.h>

// Dims
#define Bn 32
#define Sn 128
#define Pn 32
#define In 512
#define Hn 512
#define G3 1536
#define On 10

// Output layout: out[32,10] | states[32,128,512] | context[32,512] | alpha[32,128]
#define OFF_OUT 0
#define OFF_ST  320
#define OFF_CTX 2097472
#define OFF_AL  2113856

// -------- scratch (__device__ globals; no allocations allowed) --------------
__device__ float g_conv[Sn*Bn*In];
__device__ float g_emb [Sn*Bn*In];
__device__ float g_gi0 [Sn*Bn*G3];
__device__ float g_st0 [Sn*Bn*Hn];
__device__ float g_gi1 [Sn*Bn*G3];
__device__ float g_st1 [Sn*Bn*Hn];
__device__ float g_hT  [Hn*Bn];        // h transposed: [k][b]
__device__ unsigned g_bar_count;
__device__ unsigned g_bar_gen;

// -------- helpers -----------------------------------------------------------
__device__ __forceinline__ float wred(float v) {
    #pragma unroll
    for (int o = 16; o; o >>= 1) v += __shfl_xor_sync(0xffffffffu, v, o);
    return v;
}
__device__ __forceinline__ unsigned ld_acq(unsigned* p) {
    unsigned v;
    asm volatile("ld.acquire.gpu.u32 %0,[%1];" : "=r"(v) : "l"(p));
    return v;
}
#define FMA2(d,a,b) asm("fma.rn.f32x2 %0,%1,%2,%0;" : "+l"(d) : "l"(a), "l"(b))
#define BCAST2(d,f) asm("mov.b64 %0,{%1,%1};" : "=l"(d) : "f"(f))
#define PACK2(d,x,y) asm("mov.b64 %0,{%1,%2};" : "=l"(d) : "f"(x), "f"(y))
#define UNPK2(x,y,d) asm("mov.b64 {%0,%1},%2;" : "=f"(x), "=f"(y) : "l"(d))

// ======== K1: conv-attention pooling over P (conv_b cancels in softmax) =====
__global__ __launch_bounds__(256)
void conv_pool_kernel(const float* __restrict__ in, const float* __restrict__ conv_w,
                      float* __restrict__ conv_all) {
    __shared__ float cw[In];
    __shared__ float sc[Pn];
    __shared__ float at[Pn];
    const int tid = threadIdx.x;
    const int bx = blockIdx.x;          // b*S + s
    const int b = bx >> 7, s = bx & 127;
    const float* base = in + (size_t)bx * (Pn * In);

    if (tid < 128) ((float4*)cw)[tid] = ((const float4*)conv_w)[tid];
    __syncthreads();

    const int w = tid >> 5, lane = tid & 31;
    #pragma unroll
    for (int q = 0; q < 4; q++) {
        int p = w * 4 + q;
        const float4* row = (const float4*)(base + (size_t)p * In);
        const float4* cw4 = (const float4*)cw;
        float acc = 0.f;
        for (int kk = lane; kk < 128; kk += 32) {
            float4 x = row[kk], y = cw4[kk];
            acc += x.x*y.x + x.y*y.y + x.z*y.z + x.w*y.w;
        }
        acc = wred(acc);
        if (lane == 0) sc[p] = acc;
    }
    __syncthreads();

    if (tid < 32) {
        float v = sc[tid], m = v;
        #pragma unroll
        for (int o = 16; o; o >>= 1) m = fmaxf(m, __shfl_xor_sync(0xffffffffu, m, o));
        float e = expf(v - m);
        float ssum = wred(e);
        at[tid] = e / ssum;
    }
    __syncthreads();

    float* dst = conv_all + ((size_t)s * Bn + b) * In;   // row = s*32+b
    for (int i = tid; i < In; i += 256) {
        float acc = 0.f;
        #pragma unroll 8
        for (int p = 0; p < Pn; p++) acc += at[p] * base[(size_t)p * In + i];
        dst[i] = acc;
    }
}

// ======== K2/3/5: GEMM  C[M,N] = act(A[M,512] @ W[N,512]^T + bias) ==========
#define GBM 128
#define GBN 64
#define GBK 16
__global__ __launch_bounds__(256)
void gemm_tn(const float* __restrict__ A, const float* __restrict__ W,
             const float* __restrict__ bias, float* __restrict__ C,
             int N, int act) {
    __shared__ float As[GBK][GBM + 4];
    __shared__ float Ws[GBK][GBN + 4];
    const int tid = threadIdx.x;
    const int row0 = blockIdx.y * GBM;
    const int col0 = blockIdx.x * GBN;
    const int m0 = (tid >> 4) * 8;      // 0..120
    const int n0 = (tid & 15) * 4;      // 0..60
    unsigned long long acc[8][2];
    #pragma unroll
    for (int i = 0; i < 8; i++) { acc[i][0] = 0ULL; acc[i][1] = 0ULL; }

    for (int k0 = 0; k0 < 512; k0 += GBK) {
        #pragma unroll
        for (int l = 0; l < 2; l++) {
            int t = tid + l * 256;
            int m = t & 127, kq = t >> 7;
            float4 v = *(const float4*)(A + (size_t)(row0 + m) * 512 + k0 + kq * 4);
            As[kq*4+0][m] = v.x; As[kq*4+1][m] = v.y;
            As[kq*4+2][m] = v.z; As[kq*4+3][m] = v.w;
        }
        {
            int n = tid & 63, kq = tid >> 6;
            float4 v = *(const float4*)(W + (size_t)(col0 + n) * 512 + k0 + kq * 4);
            Ws[kq*4+0][n] = v.x; Ws[kq*4+1][n] = v.y;
            Ws[kq*4+2][n] = v.z; Ws[kq*4+3][n] = v.w;
        }
        __syncthreads();
        #pragma unroll
        for (int k = 0; k < GBK; k++) {
            float4 a0 = *(const float4*)&As[k][m0];
            float4 a1 = *(const float4*)&As[k][m0 + 4];
            float4 wv = *(const float4*)&Ws[k][n0];
            unsigned long long w01, w23;
            PACK2(w01, wv.x, wv.y);
            PACK2(w23, wv.z, wv.w);
            float am[8] = {a0.x,a0.y,a0.z,a0.w,a1.x,a1.y,a1.z,a1.w};
            #pragma unroll
            for (int i = 0; i < 8; i++) {
                unsigned long long ai;
                BCAST2(ai, am[i]);
                FMA2(acc[i][0], ai, w01);
                FMA2(acc[i][1], ai, w23);
            }
        }
        __syncthreads();
    }
    float bv0 = 0.f, bv1 = 0.f, bv2 = 0.f, bv3 = 0.f;
    if (bias) {
        bv0 = bias[col0+n0]; bv1 = bias[col0+n0+1];
        bv2 = bias[col0+n0+2]; bv3 = bias[col0+n0+3];
    }
    #pragma unroll
    for (int i = 0; i < 8; i++) {
        float c0, c1, c2, c3;
        UNPK2(c0, c1, acc[i][0]);
        UNPK2(c2, c3, acc[i][1]);
        float4 o = {c0 + bv0, c1 + bv1, c2 + bv2, c3 + bv3};
        if (act == 1) {
            o.x = fminf(1.f, fmaxf(-1.f, o.x));
            o.y = fminf(1.f, fmaxf(-1.f, o.y));
            o.z = fminf(1.f, fmaxf(-1.f, o.z));
            o.w = fminf(1.f, fmaxf(-1.f, o.w));
        }
        *(float4*)(C + (size_t)(row0 + m0 + i) * N + col0 + n0) = o;
    }
}

// ======== init: zero h, reset barrier counters ==============================
__global__ void init_h_kernel() {
    int i = blockIdx.x * blockDim.x + threadIdx.x;
    if (i < Hn * Bn) g_hT[i] = 0.f;
    if (i == 0) { g_bar_count = 0; g_bar_gen = 0; }
}

// ======== GRU persistent recurrence =========================================
// grid=128 CTAs (single wave), 256 thr. CTA c owns h-columns j in [4c,4c+4).
// smem: hs[512][32] (64KB) | wp[512][2][4] f32x2 pairs (32KB) | red (6KB) | bh
#define SM_HS   0
#define SM_WP   65536
#define SM_RED  (65536 + 32768)
#define SM_BH   (65536 + 32768 + 6144)
#define GRU_SMEM (65536 + 32768 + 6144 + 64)

__global__ __launch_bounds__(256)
void gru_kernel(const float* __restrict__ gi, const float* __restrict__ Whh,
                const float* __restrict__ bhh, float* __restrict__ st_out) {
    extern __shared__ char sm[];
    float* hs = (float*)(sm + SM_HS);                      // [k*32 + b]
    unsigned long long* wp = (unsigned long long*)(sm + SM_WP);  // [k*8 + jp*4 + g]
    float2* red = (float2*)(sm + SM_RED);                  // [((ks*32+b)*2+jp)*3 + g]
    float* bh = (float*)(sm + SM_BH);                      // [12]
    const int tid = threadIdx.x;
    const int cta = blockIdx.x;
    const unsigned nCta = gridDim.x;

    // Pack W_hh slice once: pair rows (j, j+1) within gate g, pair index jp.
    #pragma unroll
    for (int r = 0; r < 12; r++) {
        int g = r >> 2, jl = r & 3, jp = jl >> 1, sel = jl & 1;
        int rowg = g * 512 + cta * 4 + jl;
        for (int k = tid; k < 512; k += 256)
            ((float*)&wp[(size_t)k * 8 + jp * 4 + g])[sel] = Whh[(size_t)rowg * 512 + k];
    }
    if (tid < 12) {
        int g = tid >> 2, jl = tid & 3;
        bh[tid] = bhh[g * 512 + cta * 4 + jl];
    }

    const int b = tid & 31, jp = (tid >> 5) & 1, ks = tid >> 6;
    const int kbeg = ks * 128, kend = kbeg + 128;

    for (int s = 0; s < 128; s++) {
        __syncthreads();
        // stage current h (written by all CTAs last step, or init zeros)
        #pragma unroll
        for (int l = 0; l < 16; l++) {
            int idx = tid + l * 256;
            ((float4*)hs)[idx] = ((const float4*)g_hT)[idx];
        }
        __syncthreads();

        // partial dots: thread (b, jp, ks) -> 3 gate f32x2 accumulators
        unsigned long long a0 = 0ULL, a1 = 0ULL, a2 = 0ULL;
        const unsigned long long* wb = wp + jp * 4;
        #pragma unroll 4
        for (int k = kbeg; k < kend; k++) {
            float hk = hs[k * 32 + b];
            unsigned long long h2;
            BCAST2(h2, hk);
            ulonglong2 w01 = *(const ulonglong2*)(wb + (size_t)k * 8);
            unsigned long long w2v = wb[(size_t)k * 8 + 2];
            FMA2(a0, h2, w01.x);
            FMA2(a1, h2, w01.y);
            FMA2(a2, h2, w2v);
        }
        {
            unsigned long long* rr = (unsigned long long*)&red[((ks * 32 + b) * 2 + jp) * 3];
            rr[0] = a0; rr[1] = a1; rr[2] = a2;
        }
        __syncthreads();

        // gate math for the CTA's 4 columns (CTA-local, no extra barrier)
        if (tid < 128) {
            int bb = tid & 31, jl = tid >> 5, jpp = jl >> 1, sel = jl & 1;
            float gh0 = 0.f, gh1 = 0.f, gh2 = 0.f;
            #pragma unroll
            for (int kk = 0; kk < 4; kk++) {
                float2* q = &red[((kk * 32 + bb) * 2 + jpp) * 3];
                float2 q0 = q[0], q1 = q[1], q2 = q[2];
                gh0 += sel ? q0.y : q0.x;
                gh1 += sel ? q1.y : q1.x;
                gh2 += sel ? q2.y : q2.x;
            }
            int jg = cta * 4 + jl;
            size_t gib = ((size_t)s * 32 + bb) * (size_t)G3;
            float r = 1.f / (1.f + expf(-(gi[gib + jg]        + gh0 + bh[jl])));
            float z = 1.f / (1.f + expf(-(gi[gib + 512 + jg]  + gh1 + bh[4 + jl])));
            float nn = tanhf(gi[gib + 1024 + jg] + r * (gh2 + bh[8 + jl]));
            float ho = hs[jg * 32 + bb];
            float hn = (1.f - z) * nn + z * ho;
            g_hT[jg * 32 + bb] = hn;
            st_out[((size_t)s * 32 + bb) * 512 + jg] = hn;
        }

        // grid-wide sense barrier
        __syncthreads();
        if (tid == 0) {
            __threadfence();
            unsigned old = atomicAdd(&g_bar_count, 1);
            if (old == nCta - 1) {
                g_bar_count = 0;
                __threadfence();
                atomicAdd(&g_bar_gen, 1);
            }
            while (ld_acq(&g_bar_gen) < (unsigned)(s + 1)) __nanosleep(32);
        }
    }
}

// ======== transpose states [s][b][h] -> out [b][s][h] =======================
__global__ __launch_bounds__(256)
void transpose_states(const float* __restrict__ st1, float* __restrict__ out) {
    int bs = blockIdx.x;
    int b = bs >> 7, s = bs & 127;
    const float* src = st1 + ((size_t)s * 32 + b) * 512;
    float* dst = out + OFF_ST + ((size_t)b * 128 + s) * 512;
    for (int h = threadIdx.x; h < 512; h += 256) dst[h] = src[h];
}

// ======== final: time-attention + linear + softmax ==========================
__global__ __launch_bounds__(256)
void final_kernel(const float* __restrict__ st1, const float* __restrict__ attw,
                  const float* __restrict__ demoip, const float* __restrict__ linW,
                  const float* __restrict__ linb, float* __restrict__ out) {
    __shared__ float aw[512];
    __shared__ float lg[128];
    __shared__ float al[128];
    __shared__ float ctx[512];
    __shared__ float o10[10];
    const int tid = threadIdx.x, b = blockIdx.x;
    const int w = tid >> 5, lane = tid & 31;

    for (int h = tid; h < 512; h += 256) aw[h] = attw[h];
    __syncthreads();

    for (int s = w; s < 128; s += 8) {
        const float* row = st1 + ((size_t)s * 32 + b) * 512;
        float acc = 0.f;
        for (int h = lane; h < 512; h += 32) acc += row[h] * aw[h];
        acc = wred(acc);
        if (lane == 0) lg[s] = acc;
    }
    __syncthreads();

    if (tid < 32) {
        float v[4]; float m = -1e30f;
        #pragma unroll
        for (int q = 0; q < 4; q++) { v[q] = lg[tid + q * 32]; m = fmaxf(m, v[q]); }
        #pragma unroll
        for (int o = 16; o; o >>= 1) m = fmaxf(m, __shfl_xor_sync(0xffffffffu, m, o));
        float ssum = 0.f;
        #pragma unroll
        for (int q = 0; q < 4; q++) { v[q] = expf(v[q] - m); ssum += v[q]; }
        ssum = wred(ssum);
        #pragma unroll
        for (int q = 0; q < 4; q++) {
            float a = v[q] / ssum;
            al[tid + q * 32] = a;
            out[OFF_AL + b * 128 + tid + q * 32] = a;
        }
    }
    __syncthreads();

    for (int h = tid; h < 512; h += 256) {
        float acc = 0.f;
        for (int s = 0; s < 128; s++) acc += al[s] * st1[((size_t)s * 32 + b) * 512 + h];
        ctx[h] = acc;
        out[OFF_CTX + b * 512 + h] = acc;
    }
    __syncthreads();

    if (tid < 10) {
        float acc = linb[tid];
        const float* wrow = linW + tid * 515;
        for (int h = 0; h < 512; h++) acc += ctx[h] * wrow[h];
        for (int d = 0; d < 3; d++) acc += demoip[b * 3 + d] * wrow[512 + d];
        o10[tid] = acc;
    }
    __syncthreads();
    if (tid < 10) {
        float m = -1e30f;
        for (int o = 0; o < 10; o++) m = fmaxf(m, o10[o]);
        float e = expf(o10[tid] - m), ssum = 0.f;
        for (int o = 0; o < 10; o++) ssum += expf(o10[o] - m);
        out[OFF_OUT + b * 10 + tid] = e / ssum;
    }
}

// ======== launch ============================================================
extern "C" void kernel_launch(void* const* d_in, const int* in_sizes, int n_in,
                              void* d_out, int out_size) {
    // batch_size may or may not be materialized as input[2] (size-1 scalar).
    int sh = (in_sizes[2] == 1) ? 1 : 0;

    const float* inp   = (const float*)d_in[0];
    const float* demo  = (const float*)d_in[1];
    const float* convw = (const float*)d_in[2 + sh];
    // conv_b at [3+sh] cancels in the softmax; unused.
    const float* embW  = (const float*)d_in[4 + sh];
    const float* Wi0   = (const float*)d_in[5 + sh];
    const float* Wh0   = (const float*)d_in[6 + sh];
    const float* bi0   = (const float*)d_in[7 + sh];
    const float* bh0   = (const float*)d_in[8 + sh];
    const float* Wi1   = (const float*)d_in[9 + sh];
    const float* Wh1   = (const float*)d_in[10 + sh];
    const float* bi1   = (const float*)d_in[11 + sh];
    const float* bh1   = (const float*)d_in[12 + sh];
    const float* attw  = (const float*)d_in[13 + sh];
    const float* linW  = (const float*)d_in[14 + sh];
    const float* linb  = (const float*)d_in[15 + sh];
    float* out = (float*)d_out;

    cudaFuncSetAttribute(gru_kernel, cudaFuncAttributeMaxDynamicSharedMemorySize, GRU_SMEM);

    void *pc, *pe, *p0, *ps0, *p1, *ps1;
    cudaGetSymbolAddress(&pc, g_conv);
    cudaGetSymbolAddress(&pe, g_emb);
    cudaGetSymbolAddress(&p0, g_gi0);
    cudaGetSymbolAddress(&ps0, g_st0);
    cudaGetSymbolAddress(&p1, g_gi1);
    cudaGetSymbolAddress(&ps1, g_st1);

    conv_pool_kernel<<<Bn * Sn, 256>>>(inp, convw, (float*)pc);

    dim3 ge(In / GBN, (Sn * Bn) / GBM);   // (8, 32)
    dim3 gg(G3 / GBN, (Sn * Bn) / GBM);   // (24, 32)
    gemm_tn<<<ge, 256>>>((const float*)pc, embW, nullptr, (float*)pe, In, 1);
    gemm_tn<<<gg, 256>>>((const float*)pe, Wi0, bi0, (float*)p0, G3, 0);

    init_h_kernel<<<64, 256>>>();
    gru_kernel<<<128, 256, GRU_SMEM>>>((const float*)p0, Wh0, bh0, (float*)ps0);

    gemm_tn<<<gg, 256>>>((const float*)ps0, Wi1, bi1, (float*)p1, G3, 0);

    init_h_kernel<<<64, 256>>>();
    gru_kernel<<<128, 256, GRU_SMEM>>>((const float*)p1, Wh1, bh1, (float*)ps1);

    transpose_states<<<Bn * Sn, 256>>>((const float*)ps1, out);
    final_kernel<<<Bn, 256>>>((const float*)ps1, attw, demo, linW, linb, out);
}

// round 4
// speedup vs baseline: 1.2211x; 1.2211x over previous
#include <cuda_runtime.h>
#include <cuda_bf16.h>
#include <cstdint>
#include <cstddef>
#include <math.h>

// Dims
#define Bn 32
#define Sn 128
#define Pn 32
#define In 512
#define Hn 512
#define G3 1536
#define On 10

// Output layout: out[32,10] | states[32,128,512] | context[32,512] | alpha[32,128]
#define OFF_OUT 0
#define OFF_ST  320
#define OFF_CTX 2097472
#define OFF_AL  2113856

// -------- scratch (__device__ globals; no allocations allowed) --------------
__device__ float g_conv[Sn*Bn*In];
__device__ float g_emb [Sn*Bn*In];
__device__ float g_gi0 [Sn*Bn*G3];
__device__ float g_st0 [Sn*Bn*Hn];
__device__ float g_gi1 [Sn*Bn*G3];
__device__ float g_hT  [Hn*Bn];        // h transposed: [k][b]
__device__ unsigned g_bar_count;
__device__ unsigned g_bar_gen;

// -------- helpers -----------------------------------------------------------
__device__ __forceinline__ float wred(float v) {
    #pragma unroll
    for (int o = 16; o; o >>= 1) v += __shfl_xor_sync(0xffffffffu, v, o);
    return v;
}
__device__ __forceinline__ unsigned ld_acq(unsigned* p) {
    unsigned v;
    asm volatile("ld.acquire.gpu.u32 %0,[%1];" : "=r"(v) : "l"(p) : "memory");
    return v;
}
__device__ __forceinline__ unsigned atom_arrive_acqrel(unsigned* p) {
    unsigned o;
    asm volatile("atom.acq_rel.gpu.global.add.u32 %0,[%1],1;"
                 : "=r"(o) : "l"(p) : "memory");
    return o;
}
__device__ __forceinline__ void red_release_add(unsigned* p, unsigned v) {
    asm volatile("red.release.gpu.global.add.u32 [%0],%1;"
                 :: "l"(p), "r"(v) : "memory");
}
#define FMA2(d,a,b) asm("fma.rn.f32x2 %0,%1,%2,%0;" : "+l"(d) : "l"(a), "l"(b))
#define BCAST2(d,f) asm("mov.b64 %0,{%1,%1};" : "=l"(d) : "f"(f))
#define PACK2(d,x,y) asm("mov.b64 %0,{%1,%2};" : "=l"(d) : "f"(x), "f"(y))
#define UNPK2(x,y,d) asm("mov.b64 {%0,%1},%2;" : "=f"(x), "=f"(y) : "l"(d))

// ======== K1: conv-attention pooling over P (conv_b cancels in softmax) =====
__global__ __launch_bounds__(256)
void conv_pool_kernel(const float* __restrict__ in, const float* __restrict__ conv_w,
                      float* __restrict__ conv_all) {
    __shared__ float cw[In];
    __shared__ float sc[Pn];
    __shared__ float at[Pn];
    const int tid = threadIdx.x;
    const int bx = blockIdx.x;          // b*S + s
    const int b = bx >> 7, s = bx & 127;
    const float* base = in + (size_t)bx * (Pn * In);

    if (tid < 128) ((float4*)cw)[tid] = ((const float4*)conv_w)[tid];
    __syncthreads();

    const int w = tid >> 5, lane = tid & 31;
    #pragma unroll
    for (int q = 0; q < 4; q++) {
        int p = w * 4 + q;
        const float4* row = (const float4*)(base + (size_t)p * In);
        const float4* cw4 = (const float4*)cw;
        float acc = 0.f;
        for (int kk = lane; kk < 128; kk += 32) {
            float4 x = row[kk], y = cw4[kk];
            acc += x.x*y.x + x.y*y.y + x.z*y.z + x.w*y.w;
        }
        acc = wred(acc);
        if (lane == 0) sc[p] = acc;
    }
    __syncthreads();

    if (tid < 32) {
        float v = sc[tid], m = v;
        #pragma unroll
        for (int o = 16; o; o >>= 1) m = fmaxf(m, __shfl_xor_sync(0xffffffffu, m, o));
        float e = expf(v - m);
        float ssum = wred(e);
        at[tid] = e / ssum;
    }
    __syncthreads();

    float* dst = conv_all + ((size_t)s * Bn + b) * In;   // row = s*32+b
    for (int i = tid; i < In; i += 256) {
        float acc = 0.f;
        #pragma unroll 8
        for (int p = 0; p < Pn; p++) acc += at[p] * base[(size_t)p * In + i];
        dst[i] = acc;
    }
}

// ======== GEMM  C[M,N] = act(A[M,512] @ W[N,512]^T + bias) ==================
#define GBM 128
#define GBN 64
#define GBK 32
__global__ __launch_bounds__(256)
void gemm_tn(const float* __restrict__ A, const float* __restrict__ W,
             const float* __restrict__ bias, float* __restrict__ C,
             int N, int act) {
    __shared__ float As[GBK][GBM + 4];
    __shared__ float Ws[GBK][GBN + 4];
    const int tid = threadIdx.x;
    const int row0 = blockIdx.y * GBM;
    const int col0 = blockIdx.x * GBN;
    const int m0 = (tid >> 4) * 8;      // 0..120
    const int n0 = (tid & 15) * 4;      // 0..60
    unsigned long long acc[8][2];
    #pragma unroll
    for (int i = 0; i < 8; i++) { acc[i][0] = 0ULL; acc[i][1] = 0ULL; }

    for (int k0 = 0; k0 < 512; k0 += GBK) {
        #pragma unroll
        for (int l = 0; l < 4; l++) {
            int t = tid + l * 256;
            int m = t & 127, kq = t >> 7;   // kq 0..7
            float4 v = *(const float4*)(A + (size_t)(row0 + m) * 512 + k0 + kq * 4);
            As[kq*4+0][m] = v.x; As[kq*4+1][m] = v.y;
            As[kq*4+2][m] = v.z; As[kq*4+3][m] = v.w;
        }
        #pragma unroll
        for (int l = 0; l < 2; l++) {
            int t = tid + l * 256;
            int n = t & 63, kq = t >> 6;    // kq 0..7
            float4 v = *(const float4*)(W + (size_t)(col0 + n) * 512 + k0 + kq * 4);
            Ws[kq*4+0][n] = v.x; Ws[kq*4+1][n] = v.y;
            Ws[kq*4+2][n] = v.z; Ws[kq*4+3][n] = v.w;
        }
        __syncthreads();
        #pragma unroll
        for (int k = 0; k < GBK; k++) {
            float4 a0 = *(const float4*)&As[k][m0];
            float4 a1 = *(const float4*)&As[k][m0 + 4];
            float4 wv = *(const float4*)&Ws[k][n0];
            unsigned long long w01, w23;
            PACK2(w01, wv.x, wv.y);
            PACK2(w23, wv.z, wv.w);
            float am[8] = {a0.x,a0.y,a0.z,a0.w,a1.x,a1.y,a1.z,a1.w};
            #pragma unroll
            for (int i = 0; i < 8; i++) {
                unsigned long long ai;
                BCAST2(ai, am[i]);
                FMA2(acc[i][0], ai, w01);
                FMA2(acc[i][1], ai, w23);
            }
        }
        __syncthreads();
    }
    float bv0 = 0.f, bv1 = 0.f, bv2 = 0.f, bv3 = 0.f;
    if (bias) {
        bv0 = bias[col0+n0]; bv1 = bias[col0+n0+1];
        bv2 = bias[col0+n0+2]; bv3 = bias[col0+n0+3];
    }
    #pragma unroll
    for (int i = 0; i < 8; i++) {
        float c0, c1, c2, c3;
        UNPK2(c0, c1, acc[i][0]);
        UNPK2(c2, c3, acc[i][1]);
        float4 o = {c0 + bv0, c1 + bv1, c2 + bv2, c3 + bv3};
        if (act == 1) {
            o.x = fminf(1.f, fmaxf(-1.f, o.x));
            o.y = fminf(1.f, fmaxf(-1.f, o.y));
            o.z = fminf(1.f, fmaxf(-1.f, o.z));
            o.w = fminf(1.f, fmaxf(-1.f, o.w));
        }
        *(float4*)(C + (size_t)(row0 + m0 + i) * N + col0 + n0) = o;
    }
}

// ======== init: reset barrier counters only (h handled via s==0 path) =======
__global__ void init_bar_kernel() {
    if (threadIdx.x == 0) { g_bar_count = 0; g_bar_gen = 0; }
}

// ======== GRU persistent recurrence =========================================
// grid=128 CTAs (single wave), 256 thr. CTA c owns h-columns j in [4c,4c+4).
// smem: hs[512][32] (64KB) | wp[512][2][4] f32x2 pairs (32KB) | red (6KB) | bh
#define SM_HS   0
#define SM_WP   65536
#define SM_RED  (65536 + 32768)
#define SM_BH   (65536 + 32768 + 6144)
#define GRU_SMEM (65536 + 32768 + 6144 + 64)

__global__ __launch_bounds__(256)
void gru_kernel(const float* __restrict__ gi, const float* __restrict__ Whh,
                const float* __restrict__ bhh, float* __restrict__ st_out,
                unsigned gen_base, int lay1) {
    extern __shared__ char sm[];
    float* hs = (float*)(sm + SM_HS);                      // [k*32 + b]
    unsigned long long* wp = (unsigned long long*)(sm + SM_WP);  // [k*8 + jp*4 + g]
    float2* red = (float2*)(sm + SM_RED);                  // [((ks*32+b)*2+jp)*3 + g]
    float* bh = (float*)(sm + SM_BH);                      // [12]
    const int tid = threadIdx.x;
    const int cta = blockIdx.x;
    const unsigned nCta = gridDim.x;

    // Pack W_hh slice once: pair rows (j, j+1) within gate g, pair index jp.
    #pragma unroll
    for (int r = 0; r < 12; r++) {
        int g = r >> 2, jl = r & 3, jp = jl >> 1, sel = jl & 1;
        int rowg = g * 512 + cta * 4 + jl;
        for (int k = tid; k < 512; k += 256)
            ((float*)&wp[(size_t)k * 8 + jp * 4 + g])[sel] = Whh[(size_t)rowg * 512 + k];
    }
    if (tid < 12) {
        int g = tid >> 2, jl = tid & 3;
        bh[tid] = bhh[g * 512 + cta * 4 + jl];
    }
    __syncthreads();

    const int b = tid & 31, jp = (tid >> 5) & 1, ks = tid >> 6;   // ks uniform per warp-pair
    const int kbeg = ks * 128;
    // gate-phase identity (tid < 128)
    const int bb = tid & 31, jl = (tid >> 5) & 3;
    const int jg = cta * 4 + jl;

    for (int s = 0; s < 128; s++) {
        // ---- prefetch gi for this step (hidden under staging + dot) ----
        float giv0 = 0.f, giv1 = 0.f, giv2 = 0.f;
        if (tid < 128) {
            size_t gib = ((size_t)s * 32 + bb) * (size_t)G3;
            giv0 = __ldg(gi + gib + jg);
            giv1 = __ldg(gi + gib + 512 + jg);
            giv2 = __ldg(gi + gib + 1024 + jg);
        }

        if (s > 0) {
            // ---- stage this pair's h chunk (16KB), then pair barrier ----
            {
                const int t64 = tid & 63;
                #pragma unroll
                for (int l = 0; l < 16; l++) {
                    int idx = ks * 1024 + t64 + l * 64;
                    ((float4*)hs)[idx] = ((const float4*)g_hT)[idx];
                }
            }
            asm volatile("bar.sync %0, 64;" :: "r"(1 + ks));

            // ---- partial dots: thread (b, jp, ks) -> 3 gate f32x2 accs ----
            unsigned long long a0 = 0ULL, a1 = 0ULL, a2 = 0ULL;
            const unsigned long long* wb = wp + jp * 4;
            #pragma unroll 4
            for (int kk = 0; kk < 128; kk++) {
                int k = kbeg + kk;
                float hk = hs[k * 32 + b];
                unsigned long long h2;
                BCAST2(h2, hk);
                ulonglong2 w01 = *(const ulonglong2*)(wb + (size_t)k * 8);
                unsigned long long w2v = wb[(size_t)k * 8 + 2];
                FMA2(a0, h2, w01.x);
                FMA2(a1, h2, w01.y);
                FMA2(a2, h2, w2v);
            }
            unsigned long long* rr = (unsigned long long*)&red[((ks * 32 + b) * 2 + jp) * 3];
            rr[0] = a0; rr[1] = a1; rr[2] = a2;
        }
        __syncthreads();

        // ---- gate math for the CTA's 4 columns ----
        if (tid < 128) {
            float gh0 = 0.f, gh1 = 0.f, gh2 = 0.f, ho = 0.f;
            if (s > 0) {
                int jpp = jl >> 1, sel = jl & 1;
                #pragma unroll
                for (int kk = 0; kk < 4; kk++) {
                    float2* q = &red[((kk * 32 + bb) * 2 + jpp) * 3];
                    float2 q0 = q[0], q1 = q[1], q2 = q[2];
                    gh0 += sel ? q0.y : q0.x;
                    gh1 += sel ? q1.y : q1.x;
                    gh2 += sel ? q2.y : q2.x;
                }
                ho = hs[jg * 32 + bb];
            }
            float r = 1.f / (1.f + expf(-(giv0 + gh0 + bh[jl])));
            float z = 1.f / (1.f + expf(-(giv1 + gh1 + bh[4 + jl])));
            float nn = tanhf(giv2 + r * (gh2 + bh[8 + jl]));
            float hn = (1.f - z) * nn + z * ho;
            g_hT[jg * 32 + bb] = hn;
            size_t oidx = lay1 ? ((size_t)bb * 128 + s) * 512 + jg
                               : ((size_t)s * 32 + bb) * 512 + jg;
            st_out[oidx] = hn;
        }
        __syncthreads();

        // ---- grid-wide release/acquire barrier (no MEMBAR.GPU) ----
        if (tid == 0) {
            unsigned old = atom_arrive_acqrel(&g_bar_count);
            if (old == nCta - 1) {
                g_bar_count = 0;                 // relaxed; published by release below
                red_release_add(&g_bar_gen, 1);
            }
            unsigned target = gen_base + (unsigned)s + 1;
            while (ld_acq(&g_bar_gen) < target) { }
        }
        __syncthreads();
    }
}

// ======== final: time-attention + linear + softmax ==========================
// states layout here: [b][s][h] (written directly by layer-1 GRU into d_out)
__global__ __launch_bounds__(256)
void final_kernel(const float* __restrict__ states, const float* __restrict__ attw,
                  const float* __restrict__ demoip, const float* __restrict__ linW,
                  const float* __restrict__ linb, float* __restrict__ out) {
    __shared__ float aw[512];
    __shared__ float lg[128];
    __shared__ float al[128];
    __shared__ float ctx[512];
    __shared__ float o10[10];
    const int tid = threadIdx.x, b = blockIdx.x;
    const int w = tid >> 5, lane = tid & 31;
    const float* stb = states + (size_t)b * 128 * 512;

    for (int h = tid; h < 512; h += 256) aw[h] = attw[h];
    __syncthreads();

    for (int s = w; s < 128; s += 8) {
        const float* row = stb + (size_t)s * 512;
        float acc = 0.f;
        for (int h = lane; h < 512; h += 32) acc += row[h] * aw[h];
        acc = wred(acc);
        if (lane == 0) lg[s] = acc;
    }
    __syncthreads();

    if (tid < 32) {
        float v[4]; float m = -1e30f;
        #pragma unroll
        for (int q = 0; q < 4; q++) { v[q] = lg[tid + q * 32]; m = fmaxf(m, v[q]); }
        #pragma unroll
        for (int o = 16; o; o >>= 1) m = fmaxf(m, __shfl_xor_sync(0xffffffffu, m, o));
        float ssum = 0.f;
        #pragma unroll
        for (int q = 0; q < 4; q++) { v[q] = expf(v[q] - m); ssum += v[q]; }
        ssum = wred(ssum);
        #pragma unroll
        for (int q = 0; q < 4; q++) {
            float a = v[q] / ssum;
            al[tid + q * 32] = a;
            out[OFF_AL + b * 128 + tid + q * 32] = a;
        }
    }
    __syncthreads();

    for (int h = tid; h < 512; h += 256) {
        float acc = 0.f;
        for (int s = 0; s < 128; s++) acc += al[s] * stb[(size_t)s * 512 + h];
        ctx[h] = acc;
        out[OFF_CTX + b * 512 + h] = acc;
    }
    __syncthreads();

    if (tid < 10) {
        float acc = linb[tid];
        const float* wrow = linW + tid * 515;
        for (int h = 0; h < 512; h++) acc += ctx[h] * wrow[h];
        for (int d = 0; d < 3; d++) acc += demoip[b * 3 + d] * wrow[512 + d];
        o10[tid] = acc;
    }
    __syncthreads();
    if (tid < 10) {
        float m = -1e30f;
        for (int o = 0; o < 10; o++) m = fmaxf(m, o10[o]);
        float e = expf(o10[tid] - m), ssum = 0.f;
        for (int o = 0; o < 10; o++) ssum += expf(o10[o] - m);
        out[OFF_OUT + b * 10 + tid] = e / ssum;
    }
}

// ======== launch ============================================================
extern "C" void kernel_launch(void* const* d_in, const int* in_sizes, int n_in,
                              void* d_out, int out_size) {
    // batch_size may or may not be materialized as input[2] (size-1 scalar).
    int sh = (in_sizes[2] == 1) ? 1 : 0;

    const float* inp   = (const float*)d_in[0];
    const float* demo  = (const float*)d_in[1];
    const float* convw = (const float*)d_in[2 + sh];
    // conv_b at [3+sh] cancels in the softmax; unused.
    const float* embW  = (const float*)d_in[4 + sh];
    const float* Wi0   = (const float*)d_in[5 + sh];
    const float* Wh0   = (const float*)d_in[6 + sh];
    const float* bi0   = (const float*)d_in[7 + sh];
    const float* bh0   = (const float*)d_in[8 + sh];
    const float* Wi1   = (const float*)d_in[9 + sh];
    const float* Wh1   = (const float*)d_in[10 + sh];
    const float* bi1   = (const float*)d_in[11 + sh];
    const float* bh1   = (const float*)d_in[12 + sh];
    const float* attw  = (const float*)d_in[13 + sh];
    const float* linW  = (const float*)d_in[14 + sh];
    const float* linb  = (const float*)d_in[15 + sh];
    float* out = (float*)d_out;

    cudaFuncSetAttribute(gru_kernel, cudaFuncAttributeMaxDynamicSharedMemorySize, GRU_SMEM);

    void *pc, *pe, *p0, *ps0, *p1;
    cudaGetSymbolAddress(&pc, g_conv);
    cudaGetSymbolAddress(&pe, g_emb);
    cudaGetSymbolAddress(&p0, g_gi0);
    cudaGetSymbolAddress(&ps0, g_st0);
    cudaGetSymbolAddress(&p1, g_gi1);

    conv_pool_kernel<<<Bn * Sn, 256>>>(inp, convw, (float*)pc);

    dim3 ge(In / GBN, (Sn * Bn) / GBM);   // (8, 32)
    dim3 gg(G3 / GBN, (Sn * Bn) / GBM);   // (24, 32)
    gemm_tn<<<ge, 256>>>((const float*)pc, embW, nullptr, (float*)pe, In, 1);
    gemm_tn<<<gg, 256>>>((const float*)pe, Wi0, bi0, (float*)p0, G3, 0);

    init_bar_kernel<<<1, 32>>>();
    gru_kernel<<<128, 256, GRU_SMEM>>>((const float*)p0, Wh0, bh0, (float*)ps0, 0u, 0);

    gemm_tn<<<gg, 256>>>((const float*)ps0, Wi1, bi1, (float*)p1, G3, 0);

    gru_kernel<<<128, 256, GRU_SMEM>>>((const float*)p1, Wh1, bh1, out + OFF_ST, 128u, 1);

    final_kernel<<<Bn, 256>>>(out + OFF_ST, attw, demo, linW, linb, out);
}